// round 10
// baseline (speedup 1.0000x reference)
#include <cuda_runtime.h>
#include <cuda_fp16.h>
#include <math.h>
#include <stdint.h>

#define NTOK 65536
#define DDIM 128
#define NEXP 16
#define TOPK 3

#define KPAD 136
#define ROWB 272
#define GEMM_GX 32

__device__ int      g_cnt[NEXP];
__device__ unsigned g_list[NEXP * NTOK];
__device__ float    g_wlist[NEXP * NTOK];
__device__ __half   g_Bh[NEXP * 64 * KPAD];
__device__ __half   g_ybuf[(size_t)NTOK * TOPK * DDIM];
__device__ uint4    g_topk[NTOK];
__device__ float    g_part[512 * NEXP];

__device__ __forceinline__ uint32_t smem_u32(const void* p) {
    uint32_t a;
    asm("{ .reg .u64 t; cvta.to.shared.u64 t, %1; cvt.u32.u64 %0, t; }" : "=r"(a) : "l"(p));
    return a;
}

#define LDSM_X4(r0, r1, r2, r3, addr) \
    asm volatile("ldmatrix.sync.aligned.m8n8.x4.shared.b16 {%0,%1,%2,%3}, [%4];" \
                 : "=r"(r0), "=r"(r1), "=r"(r2), "=r"(r3) : "r"(addr))

__device__ __forceinline__ void mma16816(float* c,
    uint32_t a0, uint32_t a1, uint32_t a2, uint32_t a3, uint32_t b0, uint32_t b1)
{
    asm volatile(
        "mma.sync.aligned.m16n8k16.row.col.f32.f16.f16.f32 "
        "{%0,%1,%2,%3}, {%4,%5,%6,%7}, {%8,%9}, {%0,%1,%2,%3};"
        : "+f"(c[0]), "+f"(c[1]), "+f"(c[2]), "+f"(c[3])
        : "r"(a0), "r"(a1), "r"(a2), "r"(a3), "r"(b0), "r"(b1));
}

__global__ void __launch_bounds__(256) prepB_kernel(const float* __restrict__ We)
{
    if (blockIdx.x == 0 && blockIdx.y == 0 && threadIdx.x < NEXP)
        g_cnt[threadIdx.x] = 0;

    int e = blockIdx.x;
    const float* W = We + (size_t)e * DDIM * DDIM;
    __half* dst = g_Bh + (size_t)e * 64 * KPAD;
    int i0 = blockIdx.y * 2048 + threadIdx.x;
    for (int i = i0; i < (blockIdx.y + 1) * 2048; i += 256) {
        int n = i >> 6, kp = i & 63, k = kp * 2;
        __half2 hp;
        hp.x = __float2half(W[k * DDIM + n]);
        hp.y = __float2half(W[(k + 1) * DDIM + n]);
        *(__half2*)(dst + n * KPAD + k) = hp;
    }
}

__global__ void __launch_bounds__(128) gating_kernel(
    const float* __restrict__ x, const float* __restrict__ noise,
    const float* __restrict__ Wg, const float* __restrict__ bg,
    const float* __restrict__ Wn, const float* __restrict__ bn,
    float* __restrict__ comb)
{
    __shared__ float WgT[NEXP * DDIM];
    __shared__ float WnT[NEXP * DDIM];
    __shared__ float tw[128][3];
    __shared__ int   ti[128][3];
    __shared__ int   scnt16[NEXP];
    __shared__ int   gbase[NEXP];
    __shared__ float sred[NEXP][8];

    int tid = threadIdx.x;
    if (tid < NEXP) scnt16[tid] = 0;
    for (int i = tid; i < NEXP * DDIM; i += 128) {
        int d = i / NEXP, e = i % NEXP;
        WgT[e * DDIM + d] = Wg[i];
        WnT[e * DDIM + d] = Wn[i];
    }
    __syncthreads();

    int n = blockIdx.x * 128 + tid;

    float g[NEXP], ng[NEXP];
    #pragma unroll
    for (int e = 0; e < NEXP; e++) { g[e] = bg[e]; ng[e] = bn[e]; }

    const float4* x4 = (const float4*)(x + (size_t)n * DDIM);
    #pragma unroll 2
    for (int d4 = 0; d4 < DDIM / 4; d4++) {
        float4 xv = x4[d4];
        #pragma unroll
        for (int e = 0; e < NEXP; e++) {
            float4 a = ((const float4*)(WgT + e * DDIM))[d4];
            g[e]  += xv.x * a.x + xv.y * a.y + xv.z * a.z + xv.w * a.w;
            float4 b = ((const float4*)(WnT + e * DDIM))[d4];
            ng[e] += xv.x * b.x + xv.y * b.y + xv.z * b.z + xv.w * b.w;
        }
    }

    const float* nz = noise + (size_t)n * NEXP;
    #pragma unroll
    for (int e = 0; e < NEXP; e++) {
        float v = ng[e];
        float sp = (v > 20.f) ? v : log1pf(expf(v));
        g[e] = g[e] + nz[e] * sp;
    }

    float v0 = -INFINITY, v1 = -INFINITY, v2 = -INFINITY;
    int i0 = 0, i1 = 0, i2 = 0;
    #pragma unroll
    for (int e = 0; e < NEXP; e++) {
        float v = g[e];
        if (v > v0)      { v2 = v1; i2 = i1; v1 = v0; i1 = i0; v0 = v; i0 = e; }
        else if (v > v1) { v2 = v1; i2 = i1; v1 = v;  i1 = e; }
        else if (v > v2) { v2 = v;  i2 = e; }
    }

    float e1 = expf(v1 - v0), e2 = expf(v2 - v0);
    float s = 1.f + e1 + e2;
    float w0 = 1.f / s, w1 = e1 / s, w2 = e2 / s;

    int p0 = atomicAdd(&scnt16[i0], 1);
    int p1 = atomicAdd(&scnt16[i1], 1);
    int p2 = atomicAdd(&scnt16[i2], 1);

    tw[tid][0] = w0; tw[tid][1] = w1; tw[tid][2] = w2;
    ti[tid][0] = i0; ti[tid][1] = i1; ti[tid][2] = i2;

    {
        uint4 tk;
        tk.x = (unsigned)i0 | ((unsigned)i1 << 8) | ((unsigned)i2 << 16);
        tk.y = __float_as_uint(w0);
        tk.z = __float_as_uint(w1);
        tk.w = __float_as_uint(w2);
        g_topk[n] = tk;
    }
    __syncthreads();

    if (tid < NEXP) gbase[tid] = atomicAdd(&g_cnt[tid], scnt16[tid]);
    __syncthreads();

    {
        int q0 = gbase[i0] + p0;
        int q1 = gbase[i1] + p1;
        int q2 = gbase[i2] + p2;
        g_list[i0 * NTOK + q0] = ((unsigned)n << 2) | 0u;  g_wlist[i0 * NTOK + q0] = w0;
        g_list[i1 * NTOK + q1] = ((unsigned)n << 2) | 1u;  g_wlist[i1 * NTOK + q1] = w1;
        g_list[i2 * NTOK + q2] = ((unsigned)n << 2) | 2u;  g_wlist[i2 * NTOK + q2] = w2;
    }

    int base = blockIdx.x * 128;
    for (int i = tid; i < 128 * NEXP; i += 128) {
        int t = i >> 4, e = i & 15;
        float v = (e == ti[t][0]) ? tw[t][0]
                : (e == ti[t][1]) ? tw[t][1]
                : (e == ti[t][2]) ? tw[t][2] : 0.f;
        comb[(size_t)(base + t) * NEXP + e] = v;
    }

    {
        int e = tid & 15, j = tid >> 4;
        float ps = 0.f;
        int t0 = j * 16;
        #pragma unroll 4
        for (int t = t0; t < t0 + 16; t++) {
            if (ti[t][0] == e) ps += tw[t][0];
            if (ti[t][1] == e) ps += tw[t][1];
            if (ti[t][2] == e) ps += tw[t][2];
        }
        sred[e][j] = ps;
    }
    __syncthreads();
    if (tid < NEXP) {
        float s2 = 0.f;
        #pragma unroll
        for (int j = 0; j < 8; j++) s2 += sred[tid][j];
        g_part[blockIdx.x * NEXP + tid] = s2;
    }
}

// Hybrid GEMM: warps 0-3 HMMA cols 0..63; warps 4-7 FFMA f32x2 cols 64..127
// (1 token x 8 cols per thread per pass, 8 passes).
#define SM_A   0
#define SM_BH  34816
#define SM_B32 52224
#define SM_ENT 84992
#define SM_W   85504
#define SM_SZ  86016

__global__ void __launch_bounds__(256, 2) moe_gemm_kernel(
    const float* __restrict__ x, const float* __restrict__ We)
{
    extern __shared__ char smp[];
    uint32_t base = smem_u32(smp);

    int tid = threadIdx.x, wp = tid >> 5, ln = tid & 31;
    int e = blockIdx.y;
    int cnt = g_cnt[e];
    int ntile = (cnt + 127) >> 7;
    if ((int)blockIdx.x >= ntile) return;

    {
        const float4* bs = (const float4*)(g_Bh + (size_t)e * 64 * KPAD);
        float4* bd = (float4*)(smp + SM_BH);
        #pragma unroll 4
        for (int i = tid; i < 64 * ROWB / 16; i += 256) bd[i] = bs[i];
    }
    {
        const float* Wsrc = We + (size_t)e * DDIM * DDIM;
        float* bd = (float*)(smp + SM_B32);
        for (int i = tid; i < 8192; i += 256) {
            int k = i >> 6, n = i & 63;
            bd[i] = Wsrc[k * DDIM + 64 + n];
        }
    }

    unsigned* entS = (unsigned*)(smp + SM_ENT);
    float*    wS   = (float*)(smp + SM_W);

    int mrow = (wp & 3) * 32;
    uint32_t a_off = (uint32_t)(mrow + (ln & 15)) * ROWB + ((ln >> 4) << 4);
    uint32_t b_off = (uint32_t)((ln & 7) + ((ln >> 4) << 3)) * ROWB + (((ln >> 3) & 1) << 4);

    for (int t = blockIdx.x; t < ntile; t += GEMM_GX) {
        int rbase = t << 7;
        int mvalid = min(128, cnt - rbase);

        if (tid < 128) {
            if (tid < mvalid) {
                entS[tid] = g_list[e * NTOK + rbase + tid];
                wS[tid]   = g_wlist[e * NTOK + rbase + tid];
            } else { entS[tid] = 0xFFFFFFFFu; wS[tid] = 0.f; }
        }
        __syncthreads();

        for (int i = tid; i < 8192; i += 256) {
            int m = i >> 6, kp = i & 63;
            unsigned en = entS[m];
            uint32_t hv = 0;
            if (en != 0xFFFFFFFFu) {
                float2 v = *(const float2*)(x + (size_t)(en >> 2) * DDIM + kp * 2);
                __half2 hp; hp.x = __float2half(v.x); hp.y = __float2half(v.y);
                hv = *(uint32_t*)&hp;
            }
            *(uint32_t*)(smp + SM_A + (uint32_t)m * ROWB + (uint32_t)kp * 4) = hv;
        }
        __syncthreads();

        if (wp < 4) {
            float c[2][8][4];
            #pragma unroll
            for (int i = 0; i < 2; i++)
                #pragma unroll
                for (int j = 0; j < 8; j++)
                    #pragma unroll
                    for (int q = 0; q < 4; q++) c[i][j][q] = 0.f;

            uint32_t ab = base + SM_A + a_off;
            uint32_t bb = base + SM_BH + b_off;
            #pragma unroll
            for (int kk = 0; kk < 8; kk++) {
                uint32_t kb = (uint32_t)kk * 32;
                uint32_t a0, a1, a2, a3, a4, a5, a6, a7;
                LDSM_X4(a0, a1, a2, a3, ab + kb);
                LDSM_X4(a4, a5, a6, a7, ab + 16 * ROWB + kb);
                #pragma unroll
                for (int nw = 0; nw < 4; nw++) {
                    uint32_t b0, b1, b2, b3;
                    LDSM_X4(b0, b1, b2, b3, bb + (uint32_t)nw * 16 * ROWB + kb);
                    mma16816(c[0][nw * 2 + 0], a0, a1, a2, a3, b0, b1);
                    mma16816(c[0][nw * 2 + 1], a0, a1, a2, a3, b2, b3);
                    mma16816(c[1][nw * 2 + 0], a4, a5, a6, a7, b0, b1);
                    mma16816(c[1][nw * 2 + 1], a4, a5, a6, a7, b2, b3);
                }
            }

            int gid = ln >> 2, tig = ln & 3;
            #pragma unroll
            for (int mt = 0; mt < 2; mt++) {
                int r0 = mrow + mt * 16 + gid;
                int r1 = r0 + 8;
                unsigned e0 = entS[r0], e1 = entS[r1];
                float wa = wS[r0], wb = wS[r1];
                __half* y0 = g_ybuf + ((size_t)(e0 >> 2) * 3 + (e0 & 3u)) * DDIM;
                __half* y1 = g_ybuf + ((size_t)(e1 >> 2) * 3 + (e1 & 3u)) * DDIM;
                #pragma unroll
                for (int nt = 0; nt < 8; nt++) {
                    int col = nt * 8 + tig * 2;
                    if (e0 != 0xFFFFFFFFu) {
                        __half2 hv;
                        hv.x = __float2half(c[mt][nt][0] * wa);
                        hv.y = __float2half(c[mt][nt][1] * wa);
                        *(__half2*)(y0 + col) = hv;
                    }
                    if (e1 != 0xFFFFFFFFu) {
                        __half2 hv;
                        hv.x = __float2half(c[mt][nt][2] * wb);
                        hv.y = __float2half(c[mt][nt][3] * wb);
                        *(__half2*)(y1 + col) = hv;
                    }
                }
            }
        } else {
            // FFMA f32x2 half: token m, 8 cols per pass, 8 passes over cols 64..127
            int m = (wp - 4) * 32 + ln;
            unsigned en = entS[m];
            float wgt = wS[m];
            uint32_t arow = base + SM_A + (uint32_t)m * ROWB;
            __half* yout = g_ybuf + ((size_t)(en >> 2) * 3 + (en & 3u)) * DDIM + 64;

            #pragma unroll
            for (int pass = 0; pass < 8; pass++) {
                uint32_t bcol = base + SM_B32 + (uint32_t)pass * 32;  // 8 cols * 4B
                uint64_t acc[8];   // [0..3]: even-k partial for col pairs, [4..7]: odd-k
                #pragma unroll
                for (int j = 0; j < 8; j++) acc[j] = 0ull;

                #pragma unroll 4
                for (int k2 = 0; k2 < 64; k2++) {       // 2 k per iter
                    uint32_t ha;
                    asm volatile("ld.shared.b32 %0, [%1];" : "=r"(ha) : "r"(arow + k2 * 4));
                    float2 af = __half22float2(*(__half2*)&ha);
                    uint64_t av0, av1;
                    asm("mov.b64 %0, {%1, %1};" : "=l"(av0) : "f"(af.x));
                    asm("mov.b64 %0, {%1, %1};" : "=l"(av1) : "f"(af.y));
                    uint32_t r0 = bcol + (uint32_t)(k2 * 2) * 256;
                    uint32_t r1 = r0 + 256;
                    uint64_t b0, b1, c0, c1;
                    asm volatile("ld.shared.v2.b64 {%0,%1}, [%2];" : "=l"(b0), "=l"(b1) : "r"(r0));
                    asm volatile("ld.shared.v2.b64 {%0,%1}, [%2];" : "=l"(c0), "=l"(c1) : "r"(r1));
                    asm("fma.rn.f32x2 %0, %1, %2, %0;" : "+l"(acc[0]) : "l"(av0), "l"(b0));
                    asm("fma.rn.f32x2 %0, %1, %2, %0;" : "+l"(acc[1]) : "l"(av0), "l"(b1));
                    asm("fma.rn.f32x2 %0, %1, %2, %0;" : "+l"(acc[4]) : "l"(av1), "l"(c0));
                    asm("fma.rn.f32x2 %0, %1, %2, %0;" : "+l"(acc[5]) : "l"(av1), "l"(c1));
                    // second 4 cols of the 8-col group
                    uint64_t b2, b3, c2, c3;
                    asm volatile("ld.shared.v2.b64 {%0,%1}, [%2];" : "=l"(b2), "=l"(b3) : "r"(r0 + 16));
                    asm volatile("ld.shared.v2.b64 {%0,%1}, [%2];" : "=l"(c2), "=l"(c3) : "r"(r1 + 16));
                    asm("fma.rn.f32x2 %0, %1, %2, %0;" : "+l"(acc[2]) : "l"(av0), "l"(b2));
                    asm("fma.rn.f32x2 %0, %1, %2, %0;" : "+l"(acc[3]) : "l"(av0), "l"(b3));
                    asm("fma.rn.f32x2 %0, %1, %2, %0;" : "+l"(acc[6]) : "l"(av1), "l"(c2));
                    asm("fma.rn.f32x2 %0, %1, %2, %0;" : "+l"(acc[7]) : "l"(av1), "l"(c3));
                }

                if (en != 0xFFFFFFFFu) {
                    uint4 st;
                    uint32_t* sp32 = (uint32_t*)&st;
                    #pragma unroll
                    for (int j = 0; j < 4; j++) {
                        uint32_t lo0, hi0, lo1, hi1;
                        asm("mov.b64 {%0, %1}, %2;" : "=r"(lo0), "=r"(hi0) : "l"(acc[j]));
                        asm("mov.b64 {%0, %1}, %2;" : "=r"(lo1), "=r"(hi1) : "l"(acc[4 + j]));
                        __half2 hv;
                        hv.x = __float2half((__uint_as_float(lo0) + __uint_as_float(lo1)) * wgt);
                        hv.y = __float2half((__uint_as_float(hi0) + __uint_as_float(hi1)) * wgt);
                        sp32[j] = *(uint32_t*)&hv;
                    }
                    *(uint4*)(yout + pass * 8) = st;
                }
            }
        }
        __syncthreads();
    }
}

__global__ void __launch_bounds__(256) combine_kernel(
    const float* __restrict__ be, float* __restrict__ logits)
{
    __shared__ float beS[NEXP][DDIM];

    int tid = threadIdx.x;
    for (int i = tid; i < NEXP * DDIM; i += 256) beS[i >> 7][i & 127] = be[i];
    __syncthreads();

    size_t idx = (size_t)blockIdx.x * 256 + tid;
    int n = (int)(idx >> 4), c8 = (int)(idx & 15);
    int col = c8 * 8;

    uint4 tk = g_topk[n];
    int i0 = tk.x & 255, i1 = (tk.x >> 8) & 255, i2 = (tk.x >> 16) & 255;
    float w0 = __uint_as_float(tk.y);
    float w1 = __uint_as_float(tk.z);
    float w2 = __uint_as_float(tk.w);

    const __half* y = g_ybuf + (size_t)n * 3 * DDIM;
    uint4 p = *(const uint4*)(y + col);
    uint4 q = *(const uint4*)(y + DDIM + col);
    uint4 r = *(const uint4*)(y + 2 * DDIM + col);

    float out[8];
    {
        const uint32_t* pp = (const uint32_t*)&p;
        const uint32_t* qq = (const uint32_t*)&q;
        const uint32_t* rr = (const uint32_t*)&r;
        #pragma unroll
        for (int j = 0; j < 4; j++) {
            float2 a = __half22float2(*(__half2*)&pp[j]);
            float2 b = __half22float2(*(__half2*)&qq[j]);
            float2 d = __half22float2(*(__half2*)&rr[j]);
            out[2 * j + 0] = a.x + b.x + d.x;
            out[2 * j + 1] = a.y + b.y + d.y;
        }
    }
    #pragma unroll
    for (int half = 0; half < 2; half++) {
        int c4 = col + half * 4;
        const float4 b0 = *(const float4*)(&beS[i0][c4]);
        const float4 b1 = *(const float4*)(&beS[i1][c4]);
        const float4 b2 = *(const float4*)(&beS[i2][c4]);
        float4 a;
        a.x = out[half * 4 + 0] + w0 * b0.x + w1 * b1.x + w2 * b2.x;
        a.y = out[half * 4 + 1] + w0 * b0.y + w1 * b1.y + w2 * b2.y;
        a.z = out[half * 4 + 2] + w0 * b0.z + w1 * b1.z + w2 * b2.z;
        a.w = out[half * 4 + 3] + w0 * b0.w + w1 * b1.w + w2 * b2.w;
        *(float4*)(logits + (size_t)n * DDIM + c4) = a;
    }
}

__global__ void loss_kernel(const float* __restrict__ part, float* __restrict__ out_loss)
{
    __shared__ float red[NEXP][17];
    int tid = threadIdx.x;
    int e = tid >> 4, j = tid & 15;
    float s = 0.f;
    for (int k = 0; k < 32; k++) s += part[(j * 32 + k) * NEXP + e];
    red[e][j] = s;
    __syncthreads();
    if (tid < NEXP) {
        float t = 0.f;
        #pragma unroll
        for (int q = 0; q < 16; q++) t += red[tid][q];
        red[tid][16] = t;
    }
    __syncthreads();
    if (tid == 0) {
        float mean = 0.f;
        for (int e2 = 0; e2 < NEXP; e2++) mean += red[e2][16];
        mean /= (float)NEXP;
        float var = 0.f;
        for (int e2 = 0; e2 < NEXP; e2++) {
            float d = red[e2][16] - mean;
            var += d * d;
        }
        var /= (float)(NEXP - 1);
        out_loss[0] = var / (mean * mean);
    }
}

extern "C" void kernel_launch(void* const* d_in, const int* in_sizes, int n_in,
                              void* d_out, int out_size)
{
    const float* x     = (const float*)d_in[0];
    const float* noise = (const float*)d_in[1];
    const float* Wg    = (const float*)d_in[2];
    const float* bg    = (const float*)d_in[3];
    const float* Wn    = (const float*)d_in[4];
    const float* bn    = (const float*)d_in[5];
    const float* We    = (const float*)d_in[6];
    const float* be    = (const float*)d_in[7];

    float* out    = (float*)d_out;
    float* logits = out;
    float* lossp  = out + (size_t)NTOK * DDIM;
    float* comb   = lossp + 1;

    float* part;  cudaGetSymbolAddress((void**)&part, g_part);

    prepB_kernel<<<dim3(NEXP, 2), 256>>>(We);

    gating_kernel<<<NTOK / 128, 128>>>(x, noise, Wg, bg, Wn, bn, comb);

    loss_kernel<<<1, 256>>>(part, lossp);

    cudaFuncSetAttribute(moe_gemm_kernel,
                         cudaFuncAttributeMaxDynamicSharedMemorySize, SM_SZ);
    moe_gemm_kernel<<<dim3(GEMM_GX, NEXP), 256, SM_SZ>>>(x, We);

    combine_kernel<<<NTOK * 16 / 256, 256>>>(be, logits);

    (void)in_sizes; (void)n_in; (void)out_size;
}

// round 11
// speedup vs baseline: 3.3811x; 3.3811x over previous
#include <cuda_runtime.h>
#include <cuda_fp16.h>
#include <math.h>
#include <stdint.h>

#define NTOK 65536
#define DDIM 128
#define NEXP 16
#define TOPK 3

#define KPAD 136              // fp16 per padded row
#define ROWB 272              // bytes per padded row (16B-aligned, bank stride 4)
#define GEMM_GX 18            // 16*18=288 CTAs = one wave at 2 CTAs/SM

// ---------------------------------------------------------------------------
// Device globals
// ---------------------------------------------------------------------------
__device__ int      g_cnt[NEXP];
__device__ unsigned g_list[NEXP * NTOK];                 // (token<<2)|slot
__device__ float    g_wlist[NEXP * NTOK];
__device__ __half   g_Bh[NEXP * DDIM * KPAD];            // fp16 We^T, padded rows
__device__ __half   g_xh[(size_t)NTOK * DDIM];           // fp16 image of x (16MB)
__device__ __half   g_ybuf[(size_t)NTOK * TOPK * DDIM];  // fp16 partials (24MB)
__device__ uint4    g_topk[NTOK];
__device__ float    g_part[512 * NEXP];

// ---------------------------------------------------------------------------
// helpers
// ---------------------------------------------------------------------------
__device__ __forceinline__ uint32_t smem_u32(const void* p) {
    uint32_t a;
    asm("{ .reg .u64 t; cvta.to.shared.u64 t, %1; cvt.u32.u64 %0, t; }" : "=r"(a) : "l"(p));
    return a;
}

__device__ __forceinline__ void cp_async16(uint32_t dst, const void* src, uint32_t sz) {
    asm volatile("cp.async.ca.shared.global [%0], [%1], 16, %2;"
                 :: "r"(dst), "l"(src), "r"(sz) : "memory");
}

#define CP_COMMIT() asm volatile("cp.async.commit_group;" ::: "memory")

#define LDSM_X4(r0, r1, r2, r3, addr) \
    asm volatile("ldmatrix.sync.aligned.m8n8.x4.shared.b16 {%0,%1,%2,%3}, [%4];" \
                 : "=r"(r0), "=r"(r1), "=r"(r2), "=r"(r3) : "r"(addr))

__device__ __forceinline__ void mma16816(float* c,
    uint32_t a0, uint32_t a1, uint32_t a2, uint32_t a3, uint32_t b0, uint32_t b1)
{
    asm volatile(
        "mma.sync.aligned.m16n8k16.row.col.f32.f16.f16.f32 "
        "{%0,%1,%2,%3}, {%4,%5,%6,%7}, {%8,%9}, {%0,%1,%2,%3};"
        : "+f"(c[0]), "+f"(c[1]), "+f"(c[2]), "+f"(c[3])
        : "r"(a0), "r"(a1), "r"(a2), "r"(a3), "r"(b0), "r"(b1));
}

// ---------------------------------------------------------------------------
// prep_xh: fp16 image of x; zeroes g_cnt. grid 8192 x 256
// ---------------------------------------------------------------------------
__global__ void __launch_bounds__(256) prep_xh_kernel(const float* __restrict__ x)
{
    if (blockIdx.x == 0 && threadIdx.x < NEXP) g_cnt[threadIdx.x] = 0;
    size_t i = (size_t)blockIdx.x * 256 + threadIdx.x;   // over NTOK*DDIM/4
    float4 v = ((const float4*)x)[i];
    __half2 h0, h1;
    h0.x = __float2half(v.x); h0.y = __float2half(v.y);
    h1.x = __float2half(v.z); h1.y = __float2half(v.w);
    uint2 st;
    st.x = *(uint32_t*)&h0;
    st.y = *(uint32_t*)&h1;
    *(uint2*)(g_xh + i * 4) = st;
}

// ---------------------------------------------------------------------------
// prepB: fp16 padded image of We^T ([e][n][k], n=0..127). grid (16,4) x 256
// ---------------------------------------------------------------------------
__global__ void __launch_bounds__(256) prepB_kernel(const float* __restrict__ We)
{
    int e = blockIdx.x;
    const float* W = We + (size_t)e * DDIM * DDIM;
    __half* dst = g_Bh + (size_t)e * DDIM * KPAD;
    int i0 = blockIdx.y * 2048 + threadIdx.x;
    for (int i = i0; i < (blockIdx.y + 1) * 2048; i += 256) {
        int n = i >> 6, kp = i & 63, k = kp * 2;
        __half2 hp;
        hp.x = __float2half(W[k * DDIM + n]);
        hp.y = __float2half(W[(k + 1) * DDIM + n]);
        *(__half2*)(dst + n * KPAD + k) = hp;
    }
}

// ---------------------------------------------------------------------------
// Gating (unchanged)
// ---------------------------------------------------------------------------
__global__ void __launch_bounds__(128) gating_kernel(
    const float* __restrict__ x, const float* __restrict__ noise,
    const float* __restrict__ Wg, const float* __restrict__ bg,
    const float* __restrict__ Wn, const float* __restrict__ bn,
    float* __restrict__ comb)
{
    __shared__ float WgT[NEXP * DDIM];
    __shared__ float WnT[NEXP * DDIM];
    __shared__ float tw[128][3];
    __shared__ int   ti[128][3];
    __shared__ int   scnt16[NEXP];
    __shared__ int   gbase[NEXP];
    __shared__ float sred[NEXP][8];

    int tid = threadIdx.x;
    if (tid < NEXP) scnt16[tid] = 0;
    for (int i = tid; i < NEXP * DDIM; i += 128) {
        int d = i / NEXP, e = i % NEXP;
        WgT[e * DDIM + d] = Wg[i];
        WnT[e * DDIM + d] = Wn[i];
    }
    __syncthreads();

    int n = blockIdx.x * 128 + tid;

    float g[NEXP], ng[NEXP];
    #pragma unroll
    for (int e = 0; e < NEXP; e++) { g[e] = bg[e]; ng[e] = bn[e]; }

    const float4* x4 = (const float4*)(x + (size_t)n * DDIM);
    #pragma unroll 2
    for (int d4 = 0; d4 < DDIM / 4; d4++) {
        float4 xv = x4[d4];
        #pragma unroll
        for (int e = 0; e < NEXP; e++) {
            float4 a = ((const float4*)(WgT + e * DDIM))[d4];
            g[e]  += xv.x * a.x + xv.y * a.y + xv.z * a.z + xv.w * a.w;
            float4 b = ((const float4*)(WnT + e * DDIM))[d4];
            ng[e] += xv.x * b.x + xv.y * b.y + xv.z * b.z + xv.w * b.w;
        }
    }

    const float* nz = noise + (size_t)n * NEXP;
    #pragma unroll
    for (int e = 0; e < NEXP; e++) {
        float v = ng[e];
        float sp = (v > 20.f) ? v : log1pf(expf(v));
        g[e] = g[e] + nz[e] * sp;
    }

    float v0 = -INFINITY, v1 = -INFINITY, v2 = -INFINITY;
    int i0 = 0, i1 = 0, i2 = 0;
    #pragma unroll
    for (int e = 0; e < NEXP; e++) {
        float v = g[e];
        if (v > v0)      { v2 = v1; i2 = i1; v1 = v0; i1 = i0; v0 = v; i0 = e; }
        else if (v > v1) { v2 = v1; i2 = i1; v1 = v;  i1 = e; }
        else if (v > v2) { v2 = v;  i2 = e; }
    }

    float e1 = expf(v1 - v0), e2 = expf(v2 - v0);
    float s = 1.f + e1 + e2;
    float w0 = 1.f / s, w1 = e1 / s, w2 = e2 / s;

    int p0 = atomicAdd(&scnt16[i0], 1);
    int p1 = atomicAdd(&scnt16[i1], 1);
    int p2 = atomicAdd(&scnt16[i2], 1);

    tw[tid][0] = w0; tw[tid][1] = w1; tw[tid][2] = w2;
    ti[tid][0] = i0; ti[tid][1] = i1; ti[tid][2] = i2;

    {
        uint4 tk;
        tk.x = (unsigned)i0 | ((unsigned)i1 << 8) | ((unsigned)i2 << 16);
        tk.y = __float_as_uint(w0);
        tk.z = __float_as_uint(w1);
        tk.w = __float_as_uint(w2);
        g_topk[n] = tk;
    }
    __syncthreads();

    if (tid < NEXP) gbase[tid] = atomicAdd(&g_cnt[tid], scnt16[tid]);
    __syncthreads();

    {
        int q0 = gbase[i0] + p0;
        int q1 = gbase[i1] + p1;
        int q2 = gbase[i2] + p2;
        g_list[i0 * NTOK + q0] = ((unsigned)n << 2) | 0u;  g_wlist[i0 * NTOK + q0] = w0;
        g_list[i1 * NTOK + q1] = ((unsigned)n << 2) | 1u;  g_wlist[i1 * NTOK + q1] = w1;
        g_list[i2 * NTOK + q2] = ((unsigned)n << 2) | 2u;  g_wlist[i2 * NTOK + q2] = w2;
    }

    int base = blockIdx.x * 128;
    for (int i = tid; i < 128 * NEXP; i += 128) {
        int t = i >> 4, e = i & 15;
        float v = (e == ti[t][0]) ? tw[t][0]
                : (e == ti[t][1]) ? tw[t][1]
                : (e == ti[t][2]) ? tw[t][2] : 0.f;
        comb[(size_t)(base + t) * NEXP + e] = v;
    }

    {
        int e = tid & 15, j = tid >> 4;
        float ps = 0.f;
        int t0 = j * 16;
        #pragma unroll 4
        for (int t = t0; t < t0 + 16; t++) {
            if (ti[t][0] == e) ps += tw[t][0];
            if (ti[t][1] == e) ps += tw[t][1];
            if (ti[t][2] == e) ps += tw[t][2];
        }
        sred[e][j] = ps;
    }
    __syncthreads();
    if (tid < NEXP) {
        float s2 = 0.f;
        #pragma unroll
        for (int j = 0; j < 8; j++) s2 += sred[tid][j];
        g_part[blockIdx.x * NEXP + tid] = s2;
    }
}

// ---------------------------------------------------------------------------
// MoE GEMM: pure HMMA, double-buffered cp.async A gather.
// grid (GEMM_GX, NEXP) x 256 (8 warps, 4M x 2N, 32x64 warp tiles), 2 CTAs/SM.
// smem: A0[0,34816) A1[34816,69632) B[69632,104448)
//       ent0[104448,+512) ent1[+512) w0[105472,+512) w1[+512) => 106496 B
// ---------------------------------------------------------------------------
#define SM_A0  0
#define SM_A1  34816
#define SM_B   69632
#define SM_E0  104448
#define SM_E1  104960
#define SM_W0  105472
#define SM_W1  105984
#define SM_SZ  106496

__global__ void __launch_bounds__(256, 2) moe_gemm_kernel()
{
    extern __shared__ char smp[];
    uint32_t base = smem_u32(smp);

    int tid = threadIdx.x, wp = tid >> 5, ln = tid & 31;
    int e = blockIdx.y;
    int cnt = g_cnt[e];
    int ntile = (cnt + 127) >> 7;
    if ((int)blockIdx.x >= ntile) return;

    unsigned* entS[2] = { (unsigned*)(smp + SM_E0), (unsigned*)(smp + SM_E1) };
    float*    wSb[2]  = { (float*)(smp + SM_W0),    (float*)(smp + SM_W1) };
    const uint32_t smA[2] = { base + SM_A0, base + SM_A1 };

    // stage B via cp.async (34816 B = 2176 chunks)
    {
        const char* bsrc = (const char*)(g_Bh + (size_t)e * DDIM * KPAD);
        for (int i = tid; i < 2176; i += 256)
            cp_async16(base + SM_B + i * 16, bsrc + i * 16, 16);
    }

    // issue A gather for tile t into buffer b
    auto issue_tile = [&](int t, int b) {
        int rbase = t << 7;
        #pragma unroll
        for (int j = 0; j < 8; j++) {
            int c = tid + j * 256;            // 0..2047
            int row = c >> 4, colg = c & 15;
            int gi = rbase + row;
            unsigned en = 0xFFFFFFFFu;
            if (gi < cnt) en = g_list[e * NTOK + gi];
            unsigned tok = (en != 0xFFFFFFFFu) ? (en >> 2) : 0u;
            const __half* src = g_xh + (size_t)tok * DDIM + colg * 8;
            cp_async16(smA[b] + (uint32_t)row * ROWB + (uint32_t)colg * 16,
                       src, (en != 0xFFFFFFFFu) ? 16u : 0u);
        }
        if (tid < 128) {
            int gi = rbase + tid;
            if (gi < cnt) {
                entS[b][tid] = g_list[e * NTOK + gi];
                wSb[b][tid]  = g_wlist[e * NTOK + gi];
            } else { entS[b][tid] = 0xFFFFFFFFu; wSb[b][tid] = 0.f; }
        }
    };

    int mrow = (wp & 3) * 32;
    int ncol = (wp >> 2) * 64;
    uint32_t a_off = (uint32_t)(mrow + (ln & 15)) * ROWB + ((ln >> 4) << 4);
    uint32_t b_off = (uint32_t)(ncol + (ln & 7) + ((ln >> 4) << 3)) * ROWB + (((ln >> 3) & 1) << 4);

    issue_tile(blockIdx.x, 0);
    CP_COMMIT();

    int buf = 0;
    for (int t = blockIdx.x; t < ntile; t += GEMM_GX) {
        int tn = t + GEMM_GX;
        if (tn < ntile) {
            issue_tile(tn, buf ^ 1);
            CP_COMMIT();
            asm volatile("cp.async.wait_group 1;" ::: "memory");
        } else {
            asm volatile("cp.async.wait_group 0;" ::: "memory");
        }
        __syncthreads();

        // ---------------- MMA from buffer `buf` ----------------
        float c[2][8][4];
        #pragma unroll
        for (int i = 0; i < 2; i++)
            #pragma unroll
            for (int j = 0; j < 8; j++)
                #pragma unroll
                for (int q = 0; q < 4; q++) c[i][j][q] = 0.f;

        uint32_t ab = smA[buf] + a_off;
        uint32_t bb = base + SM_B + b_off;
        #pragma unroll
        for (int kk = 0; kk < 8; kk++) {
            uint32_t kb = (uint32_t)kk * 32;
            uint32_t a0, a1, a2, a3, a4, a5, a6, a7;
            LDSM_X4(a0, a1, a2, a3, ab + kb);
            LDSM_X4(a4, a5, a6, a7, ab + 16 * ROWB + kb);
            #pragma unroll
            for (int nw = 0; nw < 4; nw++) {
                uint32_t b0, b1, b2, b3;
                LDSM_X4(b0, b1, b2, b3, bb + (uint32_t)nw * 16 * ROWB + kb);
                mma16816(c[0][nw * 2 + 0], a0, a1, a2, a3, b0, b1);
                mma16816(c[0][nw * 2 + 1], a0, a1, a2, a3, b2, b3);
                mma16816(c[1][nw * 2 + 0], a4, a5, a6, a7, b0, b1);
                mma16816(c[1][nw * 2 + 1], a4, a5, a6, a7, b2, b3);
            }
        }

        // epilogue: scale by routing weight, direct fp16 stores
        {
            int gid = ln >> 2, tig = ln & 3;
            #pragma unroll
            for (int mt = 0; mt < 2; mt++) {
                int r0 = mrow + mt * 16 + gid;
                int r1 = r0 + 8;
                unsigned e0 = entS[buf][r0], e1 = entS[buf][r1];
                float wa = wSb[buf][r0], wb = wSb[buf][r1];
                __half* y0 = g_ybuf + ((size_t)(e0 >> 2) * 3 + (e0 & 3u)) * DDIM;
                __half* y1 = g_ybuf + ((size_t)(e1 >> 2) * 3 + (e1 & 3u)) * DDIM;
                #pragma unroll
                for (int nt = 0; nt < 8; nt++) {
                    int col = ncol + nt * 8 + tig * 2;
                    if (e0 != 0xFFFFFFFFu) {
                        __half2 hv;
                        hv.x = __float2half(c[mt][nt][0] * wa);
                        hv.y = __float2half(c[mt][nt][1] * wa);
                        *(__half2*)(y0 + col) = hv;
                    }
                    if (e1 != 0xFFFFFFFFu) {
                        __half2 hv;
                        hv.x = __float2half(c[mt][nt][2] * wb);
                        hv.y = __float2half(c[mt][nt][3] * wb);
                        *(__half2*)(y1 + col) = hv;
                    }
                }
            }
        }
        __syncthreads();   // protect buffer reuse by next issue
        buf ^= 1;
    }
}

// ---------------------------------------------------------------------------
// Combine: thread owns 8 cols of one token. grid 4096 x 256.
// ---------------------------------------------------------------------------
__global__ void __launch_bounds__(256) combine_kernel(
    const float* __restrict__ be, float* __restrict__ logits)
{
    __shared__ float beS[NEXP][DDIM];

    int tid = threadIdx.x;
    for (int i = tid; i < NEXP * DDIM; i += 256) beS[i >> 7][i & 127] = be[i];
    __syncthreads();

    size_t idx = (size_t)blockIdx.x * 256 + tid;
    int n = (int)(idx >> 4), c8 = (int)(idx & 15);
    int col = c8 * 8;

    uint4 tk = g_topk[n];
    int i0 = tk.x & 255, i1 = (tk.x >> 8) & 255, i2 = (tk.x >> 16) & 255;
    float w0 = __uint_as_float(tk.y);
    float w1 = __uint_as_float(tk.z);
    float w2 = __uint_as_float(tk.w);

    const __half* y = g_ybuf + (size_t)n * 3 * DDIM;
    uint4 p = *(const uint4*)(y + col);
    uint4 q = *(const uint4*)(y + DDIM + col);
    uint4 r = *(const uint4*)(y + 2 * DDIM + col);

    float out[8];
    {
        const uint32_t* pp = (const uint32_t*)&p;
        const uint32_t* qq = (const uint32_t*)&q;
        const uint32_t* rr = (const uint32_t*)&r;
        #pragma unroll
        for (int j = 0; j < 4; j++) {
            float2 a = __half22float2(*(__half2*)&pp[j]);
            float2 b = __half22float2(*(__half2*)&qq[j]);
            float2 d = __half22float2(*(__half2*)&rr[j]);
            out[2 * j + 0] = a.x + b.x + d.x;
            out[2 * j + 1] = a.y + b.y + d.y;
        }
    }
    #pragma unroll
    for (int half = 0; half < 2; half++) {
        int c4 = col + half * 4;
        const float4 b0 = *(const float4*)(&beS[i0][c4]);
        const float4 b1 = *(const float4*)(&beS[i1][c4]);
        const float4 b2 = *(const float4*)(&beS[i2][c4]);
        float4 a;
        a.x = out[half * 4 + 0] + w0 * b0.x + w1 * b1.x + w2 * b2.x;
        a.y = out[half * 4 + 1] + w0 * b0.y + w1 * b1.y + w2 * b2.y;
        a.z = out[half * 4 + 2] + w0 * b0.z + w1 * b1.z + w2 * b2.z;
        a.w = out[half * 4 + 3] + w0 * b0.w + w1 * b1.w + w2 * b2.w;
        *(float4*)(logits + (size_t)n * DDIM + c4) = a;
    }
}

// ---------------------------------------------------------------------------
// Loss (unchanged)
// ---------------------------------------------------------------------------
__global__ void loss_kernel(const float* __restrict__ part, float* __restrict__ out_loss)
{
    __shared__ float red[NEXP][17];
    int tid = threadIdx.x;
    int e = tid >> 4, j = tid & 15;
    float s = 0.f;
    for (int k = 0; k < 32; k++) s += part[(j * 32 + k) * NEXP + e];
    red[e][j] = s;
    __syncthreads();
    if (tid < NEXP) {
        float t = 0.f;
        #pragma unroll
        for (int q = 0; q < 16; q++) t += red[tid][q];
        red[tid][16] = t;
    }
    __syncthreads();
    if (tid == 0) {
        float mean = 0.f;
        for (int e2 = 0; e2 < NEXP; e2++) mean += red[e2][16];
        mean /= (float)NEXP;
        float var = 0.f;
        for (int e2 = 0; e2 < NEXP; e2++) {
            float d = red[e2][16] - mean;
            var += d * d;
        }
        var /= (float)(NEXP - 1);
        out_loss[0] = var / (mean * mean);
    }
}

// ---------------------------------------------------------------------------
extern "C" void kernel_launch(void* const* d_in, const int* in_sizes, int n_in,
                              void* d_out, int out_size)
{
    const float* x     = (const float*)d_in[0];
    const float* noise = (const float*)d_in[1];
    const float* Wg    = (const float*)d_in[2];
    const float* bg    = (const float*)d_in[3];
    const float* Wn    = (const float*)d_in[4];
    const float* bn    = (const float*)d_in[5];
    const float* We    = (const float*)d_in[6];
    const float* be    = (const float*)d_in[7];

    float* out    = (float*)d_out;
    float* logits = out;
    float* lossp  = out + (size_t)NTOK * DDIM;
    float* comb   = lossp + 1;

    float* part;  cudaGetSymbolAddress((void**)&part, g_part);

    prep_xh_kernel<<<NTOK * DDIM / 4 / 256, 256>>>(x);   // (1) + zero g_cnt

    prepB_kernel<<<dim3(NEXP, 4), 256>>>(We);            // (2)

    gating_kernel<<<NTOK / 128, 128>>>(x, noise, Wg, bg, Wn, bn, comb);  // (3)

    cudaFuncSetAttribute(moe_gemm_kernel,
                         cudaFuncAttributeMaxDynamicSharedMemorySize, SM_SZ);
    moe_gemm_kernel<<<dim3(GEMM_GX, NEXP), 256, SM_SZ>>>();  // (4) <- profiled slot

    loss_kernel<<<1, 256>>>(part, lossp);                // (5)

    combine_kernel<<<NTOK * 16 / 256, 256>>>(be, logits);  // (6)

    (void)in_sizes; (void)n_in; (void)out_size;
}